// round 7
// baseline (speedup 1.0000x reference)
#include <cuda_runtime.h>
#include <math.h>

#define Nn 16384
#define Dd 512
#define Kk 1024
#define NUM_ITERS 10
#define TEMPERATURE 0.1f
#define CONCENTRATION 0.1f
#define EPSf 1e-6f

#define NCHUNK 64
#define CHUNK  256

// ---------------- device scratch ----------------
__device__ float  g_cent[Kk * Dd];
__device__ float  g_xsq[Nn];
__device__ float  g_csq[Kk];
__device__ int    g_asg[Nn];
__device__ int    g_counts[Kk];
__device__ int    g_offsets[Kk];
__device__ int    g_hist[NCHUNK * Kk];
__device__ int    g_order[Nn];
__device__ float  g_dists[Kk * Dd];
__device__ double g_part1[256];
__device__ double g_part2a[256];
__device__ double g_part2b[256];
__device__ double g_S;

__global__ void copy_init_kernel(const float* __restrict__ feats) {
    int i = blockIdx.x * blockDim.x + threadIdx.x;
    if (i < Kk * Dd) g_cent[i] = feats[i];
}

__global__ void xsq_kernel(const float* __restrict__ x) {
    int warp = (blockIdx.x * blockDim.x + threadIdx.x) >> 5;
    int lane = threadIdx.x & 31;
    if (warp >= Nn) return;
    const float4* r = (const float4*)(x + (size_t)warp * Dd);
    float s = 0.f;
#pragma unroll
    for (int i = 0; i < Dd / 128; i++) {
        float4 v = r[lane + i * 32];
        s += v.x * v.x + v.y * v.y + v.z * v.z + v.w * v.w;
    }
#pragma unroll
    for (int o = 16; o; o >>= 1) s += __shfl_xor_sync(0xffffffffu, s, o);
    if (lane == 0) g_xsq[warp] = s;
}

__global__ void csq_kernel() {
    int warp = (blockIdx.x * blockDim.x + threadIdx.x) >> 5;
    int lane = threadIdx.x & 31;
    if (warp >= Kk) return;
    const float4* r = (const float4*)(g_cent + (size_t)warp * Dd);
    float s = 0.f;
#pragma unroll
    for (int i = 0; i < Dd / 128; i++) {
        float4 v = r[lane + i * 32];
        s += v.x * v.x + v.y * v.y + v.z * v.z + v.w * v.w;
    }
#pragma unroll
    for (int o = 16; o; o >>= 1) s += __shfl_xor_sync(0xffffffffu, s, o);
    if (lane == 0) g_csq[warp] = s;
}

// ---------------- assignment: tiled GEMM + argmin, FFMA2 ----------------
// BM=64 rows/block, BN=128 clusters per chunk (8 chunks), BK=16, 128 threads,
// 8x8 micro-tile = 4 row-pairs x 8 cols. B stored DUPLICATED in smem so both
// FFMA2 operands come straight out of LDS.128 halves (no packing movs).
#define BM 64
#define BN 128
#define BKC 16
#define NIT ((Kk / BN) * (Dd / BKC))   // 8 * 32 = 256
#define APAD 4
#define BROW (2 * BN + APAD)           // 260 floats per d-row of Bsd

#define LOAD_TILE(it_, buf_)                                                      \
    do {                                                                          \
        int ck_ = ((it_) >> 5) << 7;                                              \
        int d0_ = ((it_) & 31) << 4;                                              \
        _Pragma("unroll")                                                         \
        for (int u_ = 0; u_ < 2; u_++) {                                          \
            int idx_ = tid + u_ * 128;                                            \
            int row_ = idx_ >> 2, q_ = idx_ & 3;                                  \
            float4 v_ = *(const float4*)(feats + (size_t)(row0 + row_) * Dd +     \
                                         d0_ + q_ * 4);                           \
            As[buf_][q_ * 4 + 0][row_] = v_.x;                                    \
            As[buf_][q_ * 4 + 1][row_] = v_.y;                                    \
            As[buf_][q_ * 4 + 2][row_] = v_.z;                                    \
            As[buf_][q_ * 4 + 3][row_] = v_.w;                                    \
        }                                                                         \
        _Pragma("unroll")                                                         \
        for (int u_ = 0; u_ < 4; u_++) {                                          \
            int idx_ = tid + u_ * 128;                                            \
            int row_ = idx_ >> 2, q_ = idx_ & 3;                                  \
            float4 w_ = *(const float4*)(g_cent + (size_t)(ck_ + row_) * Dd +     \
                                         d0_ + q_ * 4);                           \
            Bsd[buf_][q_ * 4 + 0][2 * row_]     = w_.x;                           \
            Bsd[buf_][q_ * 4 + 0][2 * row_ + 1] = w_.x;                           \
            Bsd[buf_][q_ * 4 + 1][2 * row_]     = w_.y;                           \
            Bsd[buf_][q_ * 4 + 1][2 * row_ + 1] = w_.y;                           \
            Bsd[buf_][q_ * 4 + 2][2 * row_]     = w_.z;                           \
            Bsd[buf_][q_ * 4 + 2][2 * row_ + 1] = w_.z;                           \
            Bsd[buf_][q_ * 4 + 3][2 * row_]     = w_.w;                           \
            Bsd[buf_][q_ * 4 + 3][2 * row_ + 1] = w_.w;                           \
        }                                                                         \
    } while (0)

__global__ __launch_bounds__(128, 3) void assign_kernel(const float* __restrict__ feats) {
    __shared__ __align__(16) float As[2][BKC][BM + APAD];
    __shared__ __align__(16) float Bsd[2][BKC][BROW];

    int tid = threadIdx.x;
    int ty  = tid >> 4;   // 0..7  -> rows ty*8 .. +7
    int tx  = tid & 15;   // 0..15 -> cols tx*8 .. +7 within chunk
    int row0 = blockIdx.x * BM;

    float xs[8], best[8];
    int bidx[8];
#pragma unroll
    for (int i = 0; i < 8; i++) {
        xs[i] = g_xsq[row0 + ty * 8 + i];
        best[i] = 3.4e38f;
        bidx[i] = 0;
    }

    // acc2[p][j]: packed f32x2 for rows (2p, 2p+1), column j
    unsigned long long acc2[4][8];
#pragma unroll
    for (int p = 0; p < 4; p++)
#pragma unroll
        for (int j = 0; j < 8; j++) acc2[p][j] = 0ull;

    LOAD_TILE(0, 0);
    __syncthreads();

    int buf = 0;
    for (int it = 0; it < NIT; it++) {
        if (it + 1 < NIT) LOAD_TILE(it + 1, buf ^ 1);

#pragma unroll
        for (int d = 0; d < BKC; d++) {
            // 8 A rows arrive as two 128-bit loads = four packed row-pairs
            ulonglong2 aA = *(const ulonglong2*)&As[buf][d][ty * 8];
            ulonglong2 aB = *(const ulonglong2*)&As[buf][d][ty * 8 + 4];
            unsigned long long ap[4] = {aA.x, aA.y, aB.x, aB.y};
            // 8 duplicated B cols arrive as four 128-bit loads = eight (b,b) pairs
            ulonglong2 b0 = *(const ulonglong2*)&Bsd[buf][d][tx * 16];
            ulonglong2 b1 = *(const ulonglong2*)&Bsd[buf][d][tx * 16 + 4];
            ulonglong2 b2 = *(const ulonglong2*)&Bsd[buf][d][tx * 16 + 8];
            ulonglong2 b3 = *(const ulonglong2*)&Bsd[buf][d][tx * 16 + 12];
            unsigned long long bd2[8] = {b0.x, b0.y, b1.x, b1.y,
                                         b2.x, b2.y, b3.x, b3.y};
#pragma unroll
            for (int j = 0; j < 8; j++)
#pragma unroll
                for (int p = 0; p < 4; p++)
                    asm("fma.rn.f32x2 %0, %1, %2, %0;"
                        : "+l"(acc2[p][j]) : "l"(ap[p]), "l"(bd2[j]));
        }

        if ((it & 31) == 31) {
            int ck = (it >> 5) << 7;
#pragma unroll
            for (int j = 0; j < 8; j++) {
                int c = ck + tx * 8 + j;
                float cs = g_csq[c];
#pragma unroll
                for (int p = 0; p < 4; p++) {
                    unsigned int lo, hi;
                    asm("mov.b64 {%0, %1}, %2;" : "=r"(lo), "=r"(hi) : "l"(acc2[p][j]));
                    float d0v = xs[2 * p]     - 2.0f * __uint_as_float(lo) + cs;
                    float d1v = xs[2 * p + 1] - 2.0f * __uint_as_float(hi) + cs;
                    if (d0v < best[2 * p])     { best[2 * p]     = d0v; bidx[2 * p]     = c; }
                    if (d1v < best[2 * p + 1]) { best[2 * p + 1] = d1v; bidx[2 * p + 1] = c; }
                    acc2[p][j] = 0ull;
                }
            }
        }
        __syncthreads();
        buf ^= 1;
    }

    // argmin across the 16 column-threads of each row (within half-warp)
#pragma unroll
    for (int i = 0; i < 8; i++) {
        float bdv = best[i];
        int   biv = bidx[i];
#pragma unroll
        for (int o = 8; o; o >>= 1) {
            float od = __shfl_xor_sync(0xffffffffu, bdv, o);
            int   oi = __shfl_xor_sync(0xffffffffu, biv, o);
            if (od < bdv || (od == bdv && oi < biv)) { bdv = od; biv = oi; }
        }
        if (tx == 0) g_asg[row0 + ty * 8 + i] = biv;
    }
}

// ---------------- deterministic stable counting sort ----------------
__global__ void histo_kernel() {
    __shared__ int h[Kk];
    int c = blockIdx.x;
    int t = threadIdx.x;
#pragma unroll
    for (int i = t; i < Kk; i += CHUNK) h[i] = 0;
    __syncthreads();
    int k = g_asg[c * CHUNK + t];
    atomicAdd(&h[k], 1);
    __syncthreads();
#pragma unroll
    for (int i = t; i < Kk; i += CHUNK) g_hist[c * Kk + i] = h[i];
}

__global__ void scan_kernel() {
    __shared__ int s[Kk];
    int t = threadIdx.x;
    int total = 0;
    for (int c = 0; c < NCHUNK; c++) total += g_hist[c * Kk + t];
    g_counts[t] = total;
    s[t] = total;
    __syncthreads();
    for (int o = 1; o < Kk; o <<= 1) {
        int v = (t >= o) ? s[t - o] : 0;
        __syncthreads();
        s[t] += v;
        __syncthreads();
    }
    int excl = (t == 0) ? 0 : s[t - 1];
    g_offsets[t] = excl;
    int run = excl;
    for (int c = 0; c < NCHUNK; c++) {
        int h = g_hist[c * Kk + t];
        g_hist[c * Kk + t] = run;
        run += h;
    }
}

__global__ void scatter_kernel() {
    __shared__ int ka[CHUNK];
    int c = blockIdx.x;
    int t = threadIdx.x;
    int i = c * CHUNK + t;
    int k = g_asg[i];
    ka[t] = k;
    __syncthreads();
    int rank = 0;
    for (int j = 0; j < t; j++) rank += (ka[j] == k);
    g_order[g_hist[c * Kk + k] + rank] = i;
}

__global__ void update_kernel(const float* __restrict__ feats) {
    int k = blockIdx.x;
    int cnt = g_counts[k];
    if (cnt == 0) return;
    int start = g_offsets[k];
    float inv = 1.0f / (float)cnt;
    for (int d = threadIdx.x; d < Dd; d += blockDim.x) {
        float s = 0.f;
        for (int j = 0; j < cnt; j++)
            s += feats[(size_t)g_order[start + j] * Dd + d];
        g_cent[(size_t)k * Dd + d] = s * (float)cnt * inv * inv;
    }
}

__global__ void dists_kernel(const float* __restrict__ feats) {
    int k = blockIdx.x;
    int cnt = g_counts[k];
    int start = g_offsets[k];
    for (int d = threadIdx.x; d < Dd; d += blockDim.x) {
        float c = g_cent[(size_t)k * Dd + d];
        float s = 0.f;
        for (int j = 0; j < cnt; j++) {
            float r = feats[(size_t)g_order[start + j] * Dd + d] - c;
            s = fmaf(r, r, s);
        }
        g_dists[(size_t)k * Dd + d] = s;
    }
}

__global__ void reduce1_kernel() {
    double s = 0.0;
    int stride = gridDim.x * blockDim.x;
    for (int i = blockIdx.x * blockDim.x + threadIdx.x; i < Kk * Dd; i += stride)
        s += (double)expf(-g_dists[i] / CONCENTRATION);
    __shared__ double sm[256];
    sm[threadIdx.x] = s;
    __syncthreads();
    for (int o = 128; o; o >>= 1) {
        if (threadIdx.x < o) sm[threadIdx.x] += sm[threadIdx.x + o];
        __syncthreads();
    }
    if (threadIdx.x == 0) g_part1[blockIdx.x] = sm[0];
}

__global__ void finalize1_kernel() {
    __shared__ double sm[256];
    sm[threadIdx.x] = g_part1[threadIdx.x];
    __syncthreads();
    for (int o = 128; o; o >>= 1) {
        if (threadIdx.x < o) sm[threadIdx.x] += sm[threadIdx.x + o];
        __syncthreads();
    }
    if (threadIdx.x == 0) g_S = sm[0];
}

__global__ void reduce2_kernel() {
    float Sf = (float)g_S;
    double e1 = 0.0, e2 = 0.0;
    int stride = gridDim.x * blockDim.x;
    for (int i = blockIdx.x * blockDim.x + threadIdx.x; i < Kk * Dd; i += stride) {
        float dv = g_dists[i];
        float p  = expf(-dv / CONCENTRATION);
        float q  = p / Sf;
        e1 += (double)(q * logf(q + EPSf));
        float p2 = expf(-dv / TEMPERATURE);
        e2 += (double)logf(p2 + EPSf);
    }
    __shared__ double sa[256], sb[256];
    sa[threadIdx.x] = e1;
    sb[threadIdx.x] = e2;
    __syncthreads();
    for (int o = 128; o; o >>= 1) {
        if (threadIdx.x < o) {
            sa[threadIdx.x] += sa[threadIdx.x + o];
            sb[threadIdx.x] += sb[threadIdx.x + o];
        }
        __syncthreads();
    }
    if (threadIdx.x == 0) {
        g_part2a[blockIdx.x] = sa[0];
        g_part2b[blockIdx.x] = sb[0];
    }
}

__global__ void finalize2_kernel(float* __restrict__ out) {
    __shared__ double sa[256], sb[256];
    sa[threadIdx.x] = g_part2a[threadIdx.x];
    sb[threadIdx.x] = g_part2b[threadIdx.x];
    __syncthreads();
    for (int o = 128; o; o >>= 1) {
        if (threadIdx.x < o) {
            sa[threadIdx.x] += sa[threadIdx.x + o];
            sb[threadIdx.x] += sb[threadIdx.x + o];
        }
        __syncthreads();
    }
    if (threadIdx.x == 0) {
        double kd = (double)(Kk * Dd);
        double entropy = (sa[0] / kd);
        double nll = -(sb[0] / kd);
        out[0] = (float)(entropy + nll);
    }
}

extern "C" void kernel_launch(void* const* d_in, const int* in_sizes, int n_in,
                              void* d_out, int out_size) {
    const float* feats = (const float*)d_in[0];
    float* out = (float*)d_out;
    (void)in_sizes; (void)n_in; (void)out_size;

    copy_init_kernel<<<(Kk * Dd + 255) / 256, 256>>>(feats);
    xsq_kernel<<<(Nn * 32) / 256, 256>>>(feats);

    for (int it = 0; it < NUM_ITERS; it++) {
        csq_kernel<<<(Kk * 32) / 256, 256>>>();
        assign_kernel<<<Nn / BM, 128>>>(feats);
        histo_kernel<<<NCHUNK, CHUNK>>>();
        scan_kernel<<<1, Kk>>>();
        scatter_kernel<<<NCHUNK, CHUNK>>>();
        update_kernel<<<Kk, 128>>>(feats);
    }

    csq_kernel<<<(Kk * 32) / 256, 256>>>();
    assign_kernel<<<Nn / BM, 128>>>(feats);
    histo_kernel<<<NCHUNK, CHUNK>>>();
    scan_kernel<<<1, Kk>>>();
    scatter_kernel<<<NCHUNK, CHUNK>>>();
    dists_kernel<<<Kk, 128>>>(feats);

    reduce1_kernel<<<256, 256>>>();
    finalize1_kernel<<<1, 256>>>();
    reduce2_kernel<<<256, 256>>>();
    finalize2_kernel<<<1, 256>>>(out);
}

// round 8
// speedup vs baseline: 2.2743x; 2.2743x over previous
#include <cuda_runtime.h>
#include <math.h>

#define Nn 16384
#define Dd 512
#define Kk 1024
#define NUM_ITERS 10
#define TEMPERATURE 0.1f
#define CONCENTRATION 0.1f
#define EPSf 1e-6f

#define NCHUNK 64
#define CHUNK  256

// ---------------- device scratch ----------------
__device__ float  g_cent[Kk * Dd];
__device__ float  g_xsq[Nn];
__device__ float  g_csq[Kk];
__device__ int    g_asg[Nn];
__device__ float  g_bd2[2][Nn];        // per-K-half best distance
__device__ int    g_bi2[2][Nn];        // per-K-half best index
__device__ int    g_counts[Kk];
__device__ int    g_offsets[Kk];
__device__ int    g_hist[NCHUNK * Kk];
__device__ int    g_order[Nn];
__device__ float  g_dists[Kk * Dd];
__device__ double g_part1[256];
__device__ double g_part2a[256];
__device__ double g_part2b[256];
__device__ double g_S;

__global__ void copy_init_kernel(const float* __restrict__ feats) {
    int i = blockIdx.x * blockDim.x + threadIdx.x;
    if (i < Kk * Dd) g_cent[i] = feats[i];
}

__global__ void xsq_kernel(const float* __restrict__ x) {
    int warp = (blockIdx.x * blockDim.x + threadIdx.x) >> 5;
    int lane = threadIdx.x & 31;
    if (warp >= Nn) return;
    const float4* r = (const float4*)(x + (size_t)warp * Dd);
    float s = 0.f;
#pragma unroll
    for (int i = 0; i < Dd / 128; i++) {
        float4 v = r[lane + i * 32];
        s += v.x * v.x + v.y * v.y + v.z * v.z + v.w * v.w;
    }
#pragma unroll
    for (int o = 16; o; o >>= 1) s += __shfl_xor_sync(0xffffffffu, s, o);
    if (lane == 0) g_xsq[warp] = s;
}

__global__ void csq_kernel() {
    int warp = (blockIdx.x * blockDim.x + threadIdx.x) >> 5;
    int lane = threadIdx.x & 31;
    if (warp >= Kk) return;
    const float4* r = (const float4*)(g_cent + (size_t)warp * Dd);
    float s = 0.f;
#pragma unroll
    for (int i = 0; i < Dd / 128; i++) {
        float4 v = r[lane + i * 32];
        s += v.x * v.x + v.y * v.y + v.z * v.z + v.w * v.w;
    }
#pragma unroll
    for (int o = 16; o; o >>= 1) s += __shfl_xor_sync(0xffffffffu, s, o);
    if (lane == 0) g_csq[warp] = s;
}

// ---------------- assignment: FFMA2 GEMM + argmin, K-split x2 ----------------
// Block = 64 rows x 512 clusters (half of K). BN=128 per chunk (4 chunks),
// BK=16, 128 threads. 8x8 micro-tile as 8 rows x 4 col-pairs of f32x2 accs.
// A duplicated in smem (broadcast LDS), B plain (stride-4 conflict-free LDS).
#define BM 64
#define KHALF 512
#define BN 128
#define BKC 16
#define NIT ((KHALF / BN) * (Dd / BKC))   // 4 * 32 = 128
#define APAD 4
#define AROW (2 * BM + APAD)              // 132 floats per d-row of As_dup
#define BRW  (BN + APAD)                  // 132 floats per d-row of Bs

#define LOAD_TILE(it_, buf_)                                                      \
    do {                                                                          \
        int ckg_ = kbase + (((it_) >> 5) << 7);                                   \
        int d0_ = ((it_) & 31) << 4;                                              \
        _Pragma("unroll")                                                         \
        for (int u_ = 0; u_ < 2; u_++) {                                          \
            int idx_ = tid + u_ * 128;                                            \
            int row_ = idx_ >> 2, q_ = idx_ & 3;                                  \
            float4 v_ = *(const float4*)(feats + (size_t)(row0 + row_) * Dd +     \
                                         d0_ + q_ * 4);                           \
            As_dup[buf_][q_ * 4 + 0][2 * row_]     = v_.x;                        \
            As_dup[buf_][q_ * 4 + 0][2 * row_ + 1] = v_.x;                        \
            As_dup[buf_][q_ * 4 + 1][2 * row_]     = v_.y;                        \
            As_dup[buf_][q_ * 4 + 1][2 * row_ + 1] = v_.y;                        \
            As_dup[buf_][q_ * 4 + 2][2 * row_]     = v_.z;                        \
            As_dup[buf_][q_ * 4 + 2][2 * row_ + 1] = v_.z;                        \
            As_dup[buf_][q_ * 4 + 3][2 * row_]     = v_.w;                        \
            As_dup[buf_][q_ * 4 + 3][2 * row_ + 1] = v_.w;                        \
        }                                                                         \
        _Pragma("unroll")                                                         \
        for (int u_ = 0; u_ < 4; u_++) {                                          \
            int idx_ = tid + u_ * 128;                                            \
            int row_ = idx_ >> 2, q_ = idx_ & 3;                                  \
            float4 w_ = *(const float4*)(g_cent + (size_t)(ckg_ + row_) * Dd +    \
                                         d0_ + q_ * 4);                           \
            Bs[buf_][q_ * 4 + 0][row_] = w_.x;                                    \
            Bs[buf_][q_ * 4 + 1][row_] = w_.y;                                    \
            Bs[buf_][q_ * 4 + 2][row_] = w_.z;                                    \
            Bs[buf_][q_ * 4 + 3][row_] = w_.w;                                    \
        }                                                                         \
    } while (0)

__global__ __launch_bounds__(128, 3) void assign_kernel(const float* __restrict__ feats) {
    __shared__ __align__(16) float As_dup[2][BKC][AROW];
    __shared__ __align__(16) float Bs[2][BKC][BRW];

    int tid = threadIdx.x;
    int ty  = tid >> 4;   // 0..7  -> rows ty*8 .. +7
    int tx  = tid & 15;   // 0..15 -> cols {tx*4..+3} and {64+tx*4..+3} per chunk
    int row0 = blockIdx.x * BM;
    int kh   = blockIdx.y;            // K half
    int kbase = kh * KHALF;

    float xs[8], best[8];
    int bidx[8];
#pragma unroll
    for (int i = 0; i < 8; i++) {
        xs[i] = g_xsq[row0 + ty * 8 + i];
        best[i] = 3.4e38f;
        bidx[i] = kbase;
    }

    // acc2[i][jp]: packed f32x2 = (row_i x col_c, row_i x col_c+1)
    unsigned long long acc2[8][4];
#pragma unroll
    for (int i = 0; i < 8; i++)
#pragma unroll
        for (int jp = 0; jp < 4; jp++) acc2[i][jp] = 0ull;

    LOAD_TILE(0, 0);
    __syncthreads();

    int buf = 0;
    for (int it = 0; it < NIT; it++) {
        if (it + 1 < NIT) LOAD_TILE(it + 1, buf ^ 1);

#pragma unroll
        for (int d = 0; d < BKC; d++) {
            // 8 dup rows as four broadcast LDS.128 -> (a_i, a_i) pairs
            ulonglong2 aA = *(const ulonglong2*)&As_dup[buf][d][ty * 16];
            ulonglong2 aB = *(const ulonglong2*)&As_dup[buf][d][ty * 16 + 4];
            ulonglong2 aC = *(const ulonglong2*)&As_dup[buf][d][ty * 16 + 8];
            ulonglong2 aD = *(const ulonglong2*)&As_dup[buf][d][ty * 16 + 12];
            unsigned long long ap[8] = {aA.x, aA.y, aB.x, aB.y,
                                        aC.x, aC.y, aD.x, aD.y};
            // 8 cols as two conflict-free LDS.128 -> (c, c+1) pairs
            ulonglong2 bL = *(const ulonglong2*)&Bs[buf][d][tx * 4];
            ulonglong2 bH = *(const ulonglong2*)&Bs[buf][d][64 + tx * 4];
            unsigned long long bq[4] = {bL.x, bL.y, bH.x, bH.y};
#pragma unroll
            for (int jp = 0; jp < 4; jp++)
#pragma unroll
                for (int i = 0; i < 8; i++)
                    asm("fma.rn.f32x2 %0, %1, %2, %0;"
                        : "+l"(acc2[i][jp]) : "l"(ap[i]), "l"(bq[jp]));
        }

        if ((it & 31) == 31) {
            int ck = kbase + ((it >> 5) << 7);
#pragma unroll
            for (int jp = 0; jp < 4; jp++) {
                int c = ck + ((jp < 2) ? (tx * 4 + 2 * jp) : (64 + tx * 4 + 2 * (jp - 2)));
                float cs0 = g_csq[c];
                float cs1 = g_csq[c + 1];
#pragma unroll
                for (int i = 0; i < 8; i++) {
                    unsigned int lo, hi;
                    asm("mov.b64 {%0, %1}, %2;" : "=r"(lo), "=r"(hi) : "l"(acc2[i][jp]));
                    float d0v = xs[i] - 2.0f * __uint_as_float(lo) + cs0;
                    float d1v = xs[i] - 2.0f * __uint_as_float(hi) + cs1;
                    if (d0v < best[i]) { best[i] = d0v; bidx[i] = c; }
                    if (d1v < best[i]) { best[i] = d1v; bidx[i] = c + 1; }
                    acc2[i][jp] = 0ull;
                }
            }
        }
        __syncthreads();
        buf ^= 1;
    }

    // argmin across the 16 column-threads of each row (within half-warp)
#pragma unroll
    for (int i = 0; i < 8; i++) {
        float bdv = best[i];
        int   biv = bidx[i];
#pragma unroll
        for (int o = 8; o; o >>= 1) {
            float od = __shfl_xor_sync(0xffffffffu, bdv, o);
            int   oi = __shfl_xor_sync(0xffffffffu, biv, o);
            if (od < bdv || (od == bdv && oi < biv)) { bdv = od; biv = oi; }
        }
        if (tx == 0) {
            g_bd2[kh][row0 + ty * 8 + i] = bdv;
            g_bi2[kh][row0 + ty * 8 + i] = biv;
        }
    }
}

// combine the two K-halves; half 0 wins ties (lower indices) = jnp.argmin
__global__ void combine_kernel() {
    int i = blockIdx.x * blockDim.x + threadIdx.x;
    if (i >= Nn) return;
    float d0 = g_bd2[0][i], d1 = g_bd2[1][i];
    g_asg[i] = (d1 < d0) ? g_bi2[1][i] : g_bi2[0][i];
}

// ---------------- deterministic stable counting sort ----------------
__global__ void histo_kernel() {
    __shared__ int h[Kk];
    int c = blockIdx.x;
    int t = threadIdx.x;
#pragma unroll
    for (int i = t; i < Kk; i += CHUNK) h[i] = 0;
    __syncthreads();
    int k = g_asg[c * CHUNK + t];
    atomicAdd(&h[k], 1);
    __syncthreads();
#pragma unroll
    for (int i = t; i < Kk; i += CHUNK) g_hist[c * Kk + i] = h[i];
}

__global__ void scan_kernel() {
    __shared__ int s[Kk];
    int t = threadIdx.x;
    int total = 0;
    for (int c = 0; c < NCHUNK; c++) total += g_hist[c * Kk + t];
    g_counts[t] = total;
    s[t] = total;
    __syncthreads();
    for (int o = 1; o < Kk; o <<= 1) {
        int v = (t >= o) ? s[t - o] : 0;
        __syncthreads();
        s[t] += v;
        __syncthreads();
    }
    int excl = (t == 0) ? 0 : s[t - 1];
    g_offsets[t] = excl;
    int run = excl;
    for (int c = 0; c < NCHUNK; c++) {
        int h = g_hist[c * Kk + t];
        g_hist[c * Kk + t] = run;
        run += h;
    }
}

__global__ void scatter_kernel() {
    __shared__ int ka[CHUNK];
    int c = blockIdx.x;
    int t = threadIdx.x;
    int i = c * CHUNK + t;
    int k = g_asg[i];
    ka[t] = k;
    __syncthreads();
    int rank = 0;
    for (int j = 0; j < t; j++) rank += (ka[j] == k);
    g_order[g_hist[c * Kk + k] + rank] = i;
}

__global__ void update_kernel(const float* __restrict__ feats) {
    int k = blockIdx.x;
    int cnt = g_counts[k];
    if (cnt == 0) return;
    int start = g_offsets[k];
    float inv = 1.0f / (float)cnt;
    for (int d = threadIdx.x; d < Dd; d += blockDim.x) {
        float s = 0.f;
        for (int j = 0; j < cnt; j++)
            s += feats[(size_t)g_order[start + j] * Dd + d];
        g_cent[(size_t)k * Dd + d] = s * (float)cnt * inv * inv;
    }
}

__global__ void dists_kernel(const float* __restrict__ feats) {
    int k = blockIdx.x;
    int cnt = g_counts[k];
    int start = g_offsets[k];
    for (int d = threadIdx.x; d < Dd; d += blockDim.x) {
        float c = g_cent[(size_t)k * Dd + d];
        float s = 0.f;
        for (int j = 0; j < cnt; j++) {
            float r = feats[(size_t)g_order[start + j] * Dd + d] - c;
            s = fmaf(r, r, s);
        }
        g_dists[(size_t)k * Dd + d] = s;
    }
}

__global__ void reduce1_kernel() {
    double s = 0.0;
    int stride = gridDim.x * blockDim.x;
    for (int i = blockIdx.x * blockDim.x + threadIdx.x; i < Kk * Dd; i += stride)
        s += (double)expf(-g_dists[i] / CONCENTRATION);
    __shared__ double sm[256];
    sm[threadIdx.x] = s;
    __syncthreads();
    for (int o = 128; o; o >>= 1) {
        if (threadIdx.x < o) sm[threadIdx.x] += sm[threadIdx.x + o];
        __syncthreads();
    }
    if (threadIdx.x == 0) g_part1[blockIdx.x] = sm[0];
}

__global__ void finalize1_kernel() {
    __shared__ double sm[256];
    sm[threadIdx.x] = g_part1[threadIdx.x];
    __syncthreads();
    for (int o = 128; o; o >>= 1) {
        if (threadIdx.x < o) sm[threadIdx.x] += sm[threadIdx.x + o];
        __syncthreads();
    }
    if (threadIdx.x == 0) g_S = sm[0];
}

__global__ void reduce2_kernel() {
    float Sf = (float)g_S;
    double e1 = 0.0, e2 = 0.0;
    int stride = gridDim.x * blockDim.x;
    for (int i = blockIdx.x * blockDim.x + threadIdx.x; i < Kk * Dd; i += stride) {
        float dv = g_dists[i];
        float p  = expf(-dv / CONCENTRATION);
        float q  = p / Sf;
        e1 += (double)(q * logf(q + EPSf));
        float p2 = expf(-dv / TEMPERATURE);
        e2 += (double)logf(p2 + EPSf);
    }
    __shared__ double sa[256], sb[256];
    sa[threadIdx.x] = e1;
    sb[threadIdx.x] = e2;
    __syncthreads();
    for (int o = 128; o; o >>= 1) {
        if (threadIdx.x < o) {
            sa[threadIdx.x] += sa[threadIdx.x + o];
            sb[threadIdx.x] += sb[threadIdx.x + o];
        }
        __syncthreads();
    }
    if (threadIdx.x == 0) {
        g_part2a[blockIdx.x] = sa[0];
        g_part2b[blockIdx.x] = sb[0];
    }
}

__global__ void finalize2_kernel(float* __restrict__ out) {
    __shared__ double sa[256], sb[256];
    sa[threadIdx.x] = g_part2a[threadIdx.x];
    sb[threadIdx.x] = g_part2b[threadIdx.x];
    __syncthreads();
    for (int o = 128; o; o >>= 1) {
        if (threadIdx.x < o) {
            sa[threadIdx.x] += sa[threadIdx.x + o];
            sb[threadIdx.x] += sb[threadIdx.x + o];
        }
        __syncthreads();
    }
    if (threadIdx.x == 0) {
        double kd = (double)(Kk * Dd);
        double entropy = (sa[0] / kd);
        double nll = -(sb[0] / kd);
        out[0] = (float)(entropy + nll);
    }
}

extern "C" void kernel_launch(void* const* d_in, const int* in_sizes, int n_in,
                              void* d_out, int out_size) {
    const float* feats = (const float*)d_in[0];
    float* out = (float*)d_out;
    (void)in_sizes; (void)n_in; (void)out_size;

    dim3 agrid(Nn / BM, 2);

    copy_init_kernel<<<(Kk * Dd + 255) / 256, 256>>>(feats);
    xsq_kernel<<<(Nn * 32) / 256, 256>>>(feats);

    for (int it = 0; it < NUM_ITERS; it++) {
        csq_kernel<<<(Kk * 32) / 256, 256>>>();
        assign_kernel<<<agrid, 128>>>(feats);
        combine_kernel<<<Nn / 256, 256>>>();
        histo_kernel<<<NCHUNK, CHUNK>>>();
        scan_kernel<<<1, Kk>>>();
        scatter_kernel<<<NCHUNK, CHUNK>>>();
        update_kernel<<<Kk, 128>>>(feats);
    }

    csq_kernel<<<(Kk * 32) / 256, 256>>>();
    assign_kernel<<<agrid, 128>>>(feats);
    combine_kernel<<<Nn / 256, 256>>>();
    histo_kernel<<<NCHUNK, CHUNK>>>();
    scan_kernel<<<1, Kk>>>();
    scatter_kernel<<<NCHUNK, CHUNK>>>();
    dists_kernel<<<Kk, 128>>>(feats);

    reduce1_kernel<<<256, 256>>>();
    finalize1_kernel<<<1, 256>>>();
    reduce2_kernel<<<256, 256>>>();
    finalize2_kernel<<<1, 256>>>(out);
}

// round 10
// speedup vs baseline: 4.8640x; 2.1386x over previous
#include <cuda_runtime.h>
#include <cuda_fp16.h>
#include <math.h>
#include <stdint.h>

#define Nn 16384
#define Dd 512
#define Kk 1024
#define NUM_ITERS 10
#define TEMPERATURE 0.1f
#define CONCENTRATION 0.1f
#define EPSf 1e-6f

#define NCHUNK 64
#define CHUNK  256

// ---------------- device scratch ----------------
__device__ float  g_cent[Kk * Dd];
__device__ float  g_csq[Kk];
__device__ __align__(16) __half g_fh[Nn * Dd];   // feats fp16 hi
__device__ __align__(16) __half g_fm[Nn * Dd];   // feats fp16 lo
__device__ __align__(16) __half g_ch[Kk * Dd];   // centroid fp16 hi
__device__ __align__(16) __half g_cm[Kk * Dd];   // centroid fp16 lo
__device__ int    g_asg[Nn];
__device__ float  g_bd8[8][Nn];
__device__ int    g_bi8[8][Nn];
__device__ int    g_counts[Kk];
__device__ int    g_offsets[Kk];
__device__ int    g_hist[NCHUNK * Kk];
__device__ int    g_order[Nn];
__device__ float  g_dists[Kk * Dd];
__device__ double g_part1[256];
__device__ double g_part2a[256];
__device__ double g_part2b[256];
__device__ double g_S;

__global__ void copy_init_kernel(const float* __restrict__ feats) {
    int i = blockIdx.x * blockDim.x + threadIdx.x;
    if (i < Kk * Dd) g_cent[i] = feats[i];
}

__global__ void split_feats_kernel(const float* __restrict__ feats) {
    int i = blockIdx.x * blockDim.x + threadIdx.x;
    if (i >= Nn * Dd) return;
    float x = feats[i];
    __half h = __float2half_rn(x);
    __half m = __float2half_rn(x - __half2float(h));
    g_fh[i] = h;
    g_fm[i] = m;
}

__global__ void split_cent_kernel() {
    int i = blockIdx.x * blockDim.x + threadIdx.x;
    if (i >= Kk * Dd) return;
    float x = g_cent[i];
    __half h = __float2half_rn(x);
    __half m = __float2half_rn(x - __half2float(h));
    g_ch[i] = h;
    g_cm[i] = m;
}

__global__ void csq_kernel() {
    int warp = (blockIdx.x * blockDim.x + threadIdx.x) >> 5;
    int lane = threadIdx.x & 31;
    if (warp >= Kk) return;
    const float4* r = (const float4*)(g_cent + (size_t)warp * Dd);
    float s = 0.f;
#pragma unroll
    for (int i = 0; i < Dd / 128; i++) {
        float4 v = r[lane + i * 32];
        s += v.x * v.x + v.y * v.y + v.z * v.z + v.w * v.w;
    }
#pragma unroll
    for (int o = 16; o; o >>= 1) s += __shfl_xor_sync(0xffffffffu, s, o);
    if (lane == 0) g_csq[warp] = s;
}

// ================= mma.sync (HMMA) assignment =================
// Block: 128 points x 128 clusters; grid (128, 8 N-splits); 256 threads.
// dot = xh*ch + xh*cm + xm*ch in fp32 via m16n8k16 fp16 mma.
#define TM 128
#define TN 128
#define KC 64                  // halves per d-chunk
#define NCHK2 (Dd / KC)        // 8

#define OFF_AH 0
#define OFF_AM (TM * KC * 2)                   // 16384
#define OFF_BH (2 * TM * KC * 2)               // 32768
#define OFF_BM (2 * TM * KC * 2 + TN * KC * 2) // 49152
#define SMEM_BYTES (2 * TM * KC * 2 + 2 * TN * KC * 2)  // 65536

__device__ __forceinline__ uint32_t smem_u32(const void* p) {
    uint32_t a;
    asm("{ .reg .u64 t; cvta.to.shared.u64 t, %1; cvt.u32.u64 %0, t; }" : "=r"(a) : "l"(p));
    return a;
}

__device__ __forceinline__ void ldsm_x4(uint32_t addr, uint32_t& r0, uint32_t& r1,
                                        uint32_t& r2, uint32_t& r3) {
    asm volatile("ldmatrix.sync.aligned.m8n8.x4.shared.b16 {%0,%1,%2,%3}, [%4];"
                 : "=r"(r0), "=r"(r1), "=r"(r2), "=r"(r3) : "r"(addr));
}

__device__ __forceinline__ void mma16816(float* d, const uint32_t* a, const uint32_t* b) {
    asm volatile(
        "mma.sync.aligned.m16n8k16.row.col.f32.f16.f16.f32 "
        "{%0,%1,%2,%3}, {%4,%5,%6,%7}, {%8,%9}, {%0,%1,%2,%3};"
        : "+f"(d[0]), "+f"(d[1]), "+f"(d[2]), "+f"(d[3])
        : "r"(a[0]), "r"(a[1]), "r"(a[2]), "r"(a[3]), "r"(b[0]), "r"(b[1]));
}

extern __shared__ char dsm[];

__global__ void __launch_bounds__(256, 1) assign_mma_kernel() {
    __shared__ float scsq[TN];
    __shared__ float sdist[TM][4];
    __shared__ int   sidx[TM][4];

    int tid = threadIdx.x;
    int lane = tid & 31;
    int w = tid >> 5;
    int wm = w >> 2, wn = w & 3;           // warp grid 2 x 4
    int row0 = blockIdx.x * TM;
    int nbase = blockIdx.y * TN;

    uint32_t sb = smem_u32(dsm);

    if (tid < TN) scsq[tid] = g_csq[nbase + tid];

    float acc[4][4][4];
#pragma unroll
    for (int mt = 0; mt < 4; mt++)
#pragma unroll
        for (int nt = 0; nt < 4; nt++)
#pragma unroll
            for (int r = 0; r < 4; r++) acc[mt][nt][r] = 0.f;

    // ldmatrix address components (16B-granule XOR swizzle within 128B rows)
    int arow_b = wm * 64 + (lane & 7) + ((lane >> 3) & 1) * 8;   // + mt*16
    int agrp_h = (lane >> 4);                                    // + ks*2
    int brow_b = wn * 32 + (lane & 7) + ((lane >> 4) << 3);      // + bt*16
    int bgrp_h = ((lane >> 3) & 1);

    for (int ch2 = 0; ch2 < NCHK2; ch2++) {
        int d0 = ch2 * KC;
#pragma unroll
        for (int u = 0; u < 4; u++) {
            int idx = tid + u * 256;
            int row = idx >> 3, grp = idx & 7;
            uint32_t so = (uint32_t)(((row << 3) + (grp ^ (row & 7))) * 16);
            size_t goff = (size_t)row * Dd + d0 + grp * 8;
            *(uint4*)(dsm + OFF_AH + so) = *(const uint4*)(g_fh + (size_t)row0 * Dd + goff);
            *(uint4*)(dsm + OFF_AM + so) = *(const uint4*)(g_fm + (size_t)row0 * Dd + goff);
            *(uint4*)(dsm + OFF_BH + so) = *(const uint4*)(g_ch + (size_t)nbase * Dd + goff);
            *(uint4*)(dsm + OFF_BM + so) = *(const uint4*)(g_cm + (size_t)nbase * Dd + goff);
        }
        __syncthreads();

#pragma unroll
        for (int ks = 0; ks < KC / 16; ks++) {
            uint32_t ah[4][4], am[4][4], bh[4][2], bm[4][2];
#pragma unroll
            for (int mt = 0; mt < 4; mt++) {
                int row = arow_b + mt * 16;
                int grp = ks * 2 + agrp_h;
                uint32_t so = (uint32_t)(((row << 3) + (grp ^ (row & 7))) * 16);
                ldsm_x4(sb + OFF_AH + so, ah[mt][0], ah[mt][1], ah[mt][2], ah[mt][3]);
                ldsm_x4(sb + OFF_AM + so, am[mt][0], am[mt][1], am[mt][2], am[mt][3]);
            }
#pragma unroll
            for (int bt = 0; bt < 2; bt++) {
                int row = brow_b + bt * 16;
                int grp = ks * 2 + bgrp_h;
                uint32_t so = (uint32_t)(((row << 3) + (grp ^ (row & 7))) * 16);
                ldsm_x4(sb + OFF_BH + so, bh[2 * bt][0], bh[2 * bt][1],
                        bh[2 * bt + 1][0], bh[2 * bt + 1][1]);
                ldsm_x4(sb + OFF_BM + so, bm[2 * bt][0], bm[2 * bt][1],
                        bm[2 * bt + 1][0], bm[2 * bt + 1][1]);
            }
#pragma unroll
            for (int mt = 0; mt < 4; mt++)
#pragma unroll
                for (int nt = 0; nt < 4; nt++) {
                    mma16816(acc[mt][nt], ah[mt], bh[nt]);   // hh
                    mma16816(acc[mt][nt], ah[mt], bm[nt]);   // hm
                    mma16816(acc[mt][nt], am[mt], bh[nt]);   // mh
                }
        }
        __syncthreads();
    }

    // ---------------- epilogue: distances + argmin ----------------
    int q = lane & 3, hr = lane >> 2;
#pragma unroll
    for (int mt = 0; mt < 4; mt++)
#pragma unroll
        for (int half = 0; half < 2; half++) {
            float bd = 3.4e38f;
            int bi = 0;
#pragma unroll
            for (int nt = 0; nt < 4; nt++)
#pragma unroll
                for (int j = 0; j < 2; j++) {
                    int col = wn * 32 + nt * 8 + 2 * q + j;
                    float dist = scsq[col] - 2.0f * acc[mt][nt][half * 2 + j];
                    if (dist < bd) { bd = dist; bi = col; }
                }
#pragma unroll
            for (int o = 1; o <= 2; o <<= 1) {
                float od = __shfl_xor_sync(0xffffffffu, bd, o);
                int   oi = __shfl_xor_sync(0xffffffffu, bi, o);
                if (od < bd || (od == bd && oi < bi)) { bd = od; bi = oi; }
            }
            if (q == 0) {
                int lr = wm * 64 + mt * 16 + hr + half * 8;
                sdist[lr][wn] = bd;
                sidx[lr][wn] = bi;
            }
        }
    __syncthreads();
    if (tid < TM) {
        float bd = sdist[tid][0];
        int   bi = sidx[tid][0];
#pragma unroll
        for (int s = 1; s < 4; s++) {
            float od = sdist[tid][s];
            int   oi = sidx[tid][s];
            if (od < bd || (od == bd && oi < bi)) { bd = od; bi = oi; }
        }
        g_bd8[blockIdx.y][row0 + tid] = bd;
        g_bi8[blockIdx.y][row0 + tid] = nbase + bi;
    }
}

// combine 8 N-splits; ascending split order + strict < = lowest-index tie-break
__global__ void combine_kernel() {
    int i = blockIdx.x * blockDim.x + threadIdx.x;
    if (i >= Nn) return;
    float bd = g_bd8[0][i];
    int   bi = g_bi8[0][i];
#pragma unroll
    for (int s = 1; s < 8; s++) {
        float d = g_bd8[s][i];
        if (d < bd) { bd = d; bi = g_bi8[s][i]; }
    }
    g_asg[i] = bi;
}

// ---------------- deterministic stable counting sort ----------------
__global__ void histo_kernel() {
    __shared__ int h[Kk];
    int c = blockIdx.x;
    int t = threadIdx.x;
#pragma unroll
    for (int i = t; i < Kk; i += CHUNK) h[i] = 0;
    __syncthreads();
    int k = g_asg[c * CHUNK + t];
    atomicAdd(&h[k], 1);
    __syncthreads();
#pragma unroll
    for (int i = t; i < Kk; i += CHUNK) g_hist[c * Kk + i] = h[i];
}

__global__ void scan_kernel() {
    __shared__ int s[Kk];
    int t = threadIdx.x;
    int total = 0;
    for (int c = 0; c < NCHUNK; c++) total += g_hist[c * Kk + t];
    g_counts[t] = total;
    s[t] = total;
    __syncthreads();
    for (int o = 1; o < Kk; o <<= 1) {
        int v = (t >= o) ? s[t - o] : 0;
        __syncthreads();
        s[t] += v;
        __syncthreads();
    }
    int excl = (t == 0) ? 0 : s[t - 1];
    g_offsets[t] = excl;
    int run = excl;
    for (int c = 0; c < NCHUNK; c++) {
        int h = g_hist[c * Kk + t];
        g_hist[c * Kk + t] = run;
        run += h;
    }
}

__global__ void scatter_kernel() {
    __shared__ int ka[CHUNK];
    int c = blockIdx.x;
    int t = threadIdx.x;
    int i = c * CHUNK + t;
    int k = g_asg[i];
    ka[t] = k;
    __syncthreads();
    int rank = 0;
    for (int j = 0; j < t; j++) rank += (ka[j] == k);
    g_order[g_hist[c * Kk + k] + rank] = i;
}

__global__ void update_kernel(const float* __restrict__ feats) {
    int k = blockIdx.x;
    int cnt = g_counts[k];
    if (cnt == 0) return;
    int start = g_offsets[k];
    float inv = 1.0f / (float)cnt;
    for (int d = threadIdx.x; d < Dd; d += blockDim.x) {
        float s = 0.f;
        for (int j = 0; j < cnt; j++)
            s += feats[(size_t)g_order[start + j] * Dd + d];
        g_cent[(size_t)k * Dd + d] = s * (float)cnt * inv * inv;
    }
}

__global__ void dists_kernel(const float* __restrict__ feats) {
    int k = blockIdx.x;
    int cnt = g_counts[k];
    int start = g_offsets[k];
    for (int d = threadIdx.x; d < Dd; d += blockDim.x) {
        float c = g_cent[(size_t)k * Dd + d];
        float s = 0.f;
        for (int j = 0; j < cnt; j++) {
            float r = feats[(size_t)g_order[start + j] * Dd + d] - c;
            s = fmaf(r, r, s);
        }
        g_dists[(size_t)k * Dd + d] = s;
    }
}

__global__ void reduce1_kernel() {
    double s = 0.0;
    int stride = gridDim.x * blockDim.x;
    for (int i = blockIdx.x * blockDim.x + threadIdx.x; i < Kk * Dd; i += stride)
        s += (double)expf(-g_dists[i] / CONCENTRATION);
    __shared__ double sm[256];
    sm[threadIdx.x] = s;
    __syncthreads();
    for (int o = 128; o; o >>= 1) {
        if (threadIdx.x < o) sm[threadIdx.x] += sm[threadIdx.x + o];
        __syncthreads();
    }
    if (threadIdx.x == 0) g_part1[blockIdx.x] = sm[0];
}

__global__ void finalize1_kernel() {
    __shared__ double sm[256];
    sm[threadIdx.x] = g_part1[threadIdx.x];
    __syncthreads();
    for (int o = 128; o; o >>= 1) {
        if (threadIdx.x < o) sm[threadIdx.x] += sm[threadIdx.x + o];
        __syncthreads();
    }
    if (threadIdx.x == 0) g_S = sm[0];
}

__global__ void reduce2_kernel() {
    float Sf = (float)g_S;
    double e1 = 0.0, e2 = 0.0;
    int stride = gridDim.x * blockDim.x;
    for (int i = blockIdx.x * blockDim.x + threadIdx.x; i < Kk * Dd; i += stride) {
        float dv = g_dists[i];
        float p  = expf(-dv / CONCENTRATION);
        float q  = p / Sf;
        e1 += (double)(q * logf(q + EPSf));
        float p2 = expf(-dv / TEMPERATURE);
        e2 += (double)logf(p2 + EPSf);
    }
    __shared__ double sa[256], sb[256];
    sa[threadIdx.x] = e1;
    sb[threadIdx.x] = e2;
    __syncthreads();
    for (int o = 128; o; o >>= 1) {
        if (threadIdx.x < o) {
            sa[threadIdx.x] += sa[threadIdx.x + o];
            sb[threadIdx.x] += sb[threadIdx.x + o];
        }
        __syncthreads();
    }
    if (threadIdx.x == 0) {
        g_part2a[blockIdx.x] = sa[0];
        g_part2b[blockIdx.x] = sb[0];
    }
}

__global__ void finalize2_kernel(float* __restrict__ out) {
    __shared__ double sa[256], sb[256];
    sa[threadIdx.x] = g_part2a[threadIdx.x];
    sb[threadIdx.x] = g_part2b[threadIdx.x];
    __syncthreads();
    for (int o = 128; o; o >>= 1) {
        if (threadIdx.x < o) {
            sa[threadIdx.x] += sa[threadIdx.x + o];
            sb[threadIdx.x] += sb[threadIdx.x + o];
        }
        __syncthreads();
    }
    if (threadIdx.x == 0) {
        double kd = (double)(Kk * Dd);
        double entropy = (sa[0] / kd);
        double nll = -(sb[0] / kd);
        out[0] = (float)(entropy + nll);
    }
}

extern "C" void kernel_launch(void* const* d_in, const int* in_sizes, int n_in,
                              void* d_out, int out_size) {
    const float* feats = (const float*)d_in[0];
    float* out = (float*)d_out;
    (void)in_sizes; (void)n_in; (void)out_size;

    static bool attr_done = false;
    if (!attr_done) {
        cudaFuncSetAttribute(assign_mma_kernel,
                             cudaFuncAttributeMaxDynamicSharedMemorySize, SMEM_BYTES);
        attr_done = true;
    }

    dim3 agrid(Nn / TM, Kk / TN);

    copy_init_kernel<<<(Kk * Dd + 255) / 256, 256>>>(feats);
    split_feats_kernel<<<(Nn * Dd + 255) / 256, 256>>>(feats);

    for (int it = 0; it < NUM_ITERS; it++) {
        csq_kernel<<<(Kk * 32) / 256, 256>>>();
        split_cent_kernel<<<(Kk * Dd + 255) / 256, 256>>>();
        assign_mma_kernel<<<agrid, 256, SMEM_BYTES>>>();
        combine_kernel<<<Nn / 256, 256>>>();
        histo_kernel<<<NCHUNK, CHUNK>>>();
        scan_kernel<<<1, Kk>>>();
        scatter_kernel<<<NCHUNK, CHUNK>>>();
        update_kernel<<<Kk, 128>>>(feats);
    }

    csq_kernel<<<(Kk * 32) / 256, 256>>>();
    split_cent_kernel<<<(Kk * Dd + 255) / 256, 256>>>();
    assign_mma_kernel<<<agrid, 256, SMEM_BYTES>>>();
    combine_kernel<<<Nn / 256, 256>>>();
    histo_kernel<<<NCHUNK, CHUNK>>>();
    scan_kernel<<<1, Kk>>>();
    scatter_kernel<<<NCHUNK, CHUNK>>>();
    dists_kernel<<<Kk, 128>>>(feats);

    reduce1_kernel<<<256, 256>>>();
    finalize1_kernel<<<1, 256>>>();
    reduce2_kernel<<<256, 256>>>();
    finalize2_kernel<<<1, 256>>>(out);
}

// round 11
// speedup vs baseline: 5.4897x; 1.1287x over previous
#include <cuda_runtime.h>
#include <cuda_fp16.h>
#include <math.h>
#include <stdint.h>

#define Nn 16384
#define Dd 512
#define Kk 1024
#define NUM_ITERS 10
#define TEMPERATURE 0.1f
#define CONCENTRATION 0.1f
#define EPSf 1e-6f

#define NCHUNK 64
#define CHUNK  256

// ---------------- device scratch ----------------
__device__ float  g_cent[Kk * Dd];
__device__ float  g_csq[Kk];
__device__ __align__(16) __half g_fh[Nn * Dd];   // feats fp16 hi
__device__ __align__(16) __half g_fm[Nn * Dd];   // feats fp16 lo
__device__ __align__(16) __half g_ch[Kk * Dd];   // centroid fp16 hi
__device__ __align__(16) __half g_cm[Kk * Dd];   // centroid fp16 lo
__device__ int    g_asg[Nn];
__device__ float  g_bd8[8][Nn];
__device__ int    g_bi8[8][Nn];
__device__ int    g_counts[Kk];
__device__ int    g_offsets[Kk];
__device__ int    g_hist[NCHUNK * Kk];
__device__ int    g_order[Nn];
__device__ float  g_dists[Kk * Dd];
__device__ double g_part1[256];
__device__ double g_part2a[256];
__device__ double g_part2b[256];
__device__ double g_S;

__global__ void copy_init_kernel(const float* __restrict__ feats) {
    int i = blockIdx.x * blockDim.x + threadIdx.x;
    if (i < Kk * Dd) g_cent[i] = feats[i];
}

__global__ void split_feats_kernel(const float* __restrict__ feats) {
    int i = blockIdx.x * blockDim.x + threadIdx.x;
    if (i >= Nn * Dd) return;
    float x = feats[i];
    __half h = __float2half_rn(x);
    __half m = __float2half_rn(x - __half2float(h));
    g_fh[i] = h;
    g_fm[i] = m;
}

__global__ void split_cent_kernel() {
    int i = blockIdx.x * blockDim.x + threadIdx.x;
    if (i >= Kk * Dd) return;
    float x = g_cent[i];
    __half h = __float2half_rn(x);
    __half m = __float2half_rn(x - __half2float(h));
    g_ch[i] = h;
    g_cm[i] = m;
}

__global__ void csq_kernel() {
    int warp = (blockIdx.x * blockDim.x + threadIdx.x) >> 5;
    int lane = threadIdx.x & 31;
    if (warp >= Kk) return;
    const float4* r = (const float4*)(g_cent + (size_t)warp * Dd);
    float s = 0.f;
#pragma unroll
    for (int i = 0; i < Dd / 128; i++) {
        float4 v = r[lane + i * 32];
        s += v.x * v.x + v.y * v.y + v.z * v.z + v.w * v.w;
    }
#pragma unroll
    for (int o = 16; o; o >>= 1) s += __shfl_xor_sync(0xffffffffu, s, o);
    if (lane == 0) g_csq[warp] = s;
}

// ================= mma.sync (HMMA) assignment, cp.async pipelined =========
// Block: 128 points x 128 clusters; grid (128, 8 N-splits); 256 threads.
// dot = xh*ch + xh*cm + xm*ch in fp32 via m16n8k16 fp16 mma.
// 2-stage cp.async double buffer over 8 d-chunks of 64 halves.
#define TM 128
#define TN 128
#define KC 64                  // halves per d-chunk
#define NCHK2 (Dd / KC)        // 8

#define OFF_AH 0
#define OFF_AM (TM * KC * 2)                   // 16384
#define OFF_BH (2 * TM * KC * 2)               // 32768
#define OFF_BM (2 * TM * KC * 2 + TN * KC * 2) // 49152
#define STAGE_BYTES (2 * TM * KC * 2 + 2 * TN * KC * 2)  // 65536
#define SMEM_BYTES (2 * STAGE_BYTES)                     // 131072

__device__ __forceinline__ uint32_t smem_u32(const void* p) {
    uint32_t a;
    asm("{ .reg .u64 t; cvta.to.shared.u64 t, %1; cvt.u32.u64 %0, t; }" : "=r"(a) : "l"(p));
    return a;
}

__device__ __forceinline__ void cp16(uint32_t saddr, const void* gptr) {
    asm volatile("cp.async.cg.shared.global [%0], [%1], 16;"
                 :: "r"(saddr), "l"(gptr) : "memory");
}

__device__ __forceinline__ void ldsm_x4(uint32_t addr, uint32_t& r0, uint32_t& r1,
                                        uint32_t& r2, uint32_t& r3) {
    asm volatile("ldmatrix.sync.aligned.m8n8.x4.shared.b16 {%0,%1,%2,%3}, [%4];"
                 : "=r"(r0), "=r"(r1), "=r"(r2), "=r"(r3) : "r"(addr));
}

__device__ __forceinline__ void mma16816(float* d, const uint32_t* a, const uint32_t* b) {
    asm volatile(
        "mma.sync.aligned.m16n8k16.row.col.f32.f16.f16.f32 "
        "{%0,%1,%2,%3}, {%4,%5,%6,%7}, {%8,%9}, {%0,%1,%2,%3};"
        : "+f"(d[0]), "+f"(d[1]), "+f"(d[2]), "+f"(d[3])
        : "r"(a[0]), "r"(a[1]), "r"(a[2]), "r"(a[3]), "r"(b[0]), "r"(b[1]));
}

extern __shared__ char dsm[];

__global__ void __launch_bounds__(256, 1) assign_mma_kernel() {
    __shared__ float scsq[TN];
    __shared__ float sdist[TM][4];
    __shared__ int   sidx[TM][4];

    int tid = threadIdx.x;
    int lane = tid & 31;
    int w = tid >> 5;
    int wm = w >> 2, wn = w & 3;           // warp grid 2 x 4
    int row0 = blockIdx.x * TM;
    int nbase = blockIdx.y * TN;

    uint32_t sb = smem_u32(dsm);

    if (tid < TN) scsq[tid] = g_csq[nbase + tid];

    float acc[4][4][4];
#pragma unroll
    for (int mt = 0; mt < 4; mt++)
#pragma unroll
        for (int nt = 0; nt < 4; nt++)
#pragma unroll
            for (int r = 0; r < 4; r++) acc[mt][nt][r] = 0.f;

    // per-thread load coordinates (fixed across chunks/stages)
    int lrow = tid >> 3, lgrp = tid & 7;

    // issue one chunk's loads into a stage; 1 commit group per call
#define ISSUE_CHUNK(ch_, stg_)                                                     \
    do {                                                                           \
        int d0_ = (ch_) * KC;                                                      \
        uint32_t sbase_ = sb + (stg_) * STAGE_BYTES;                               \
        _Pragma("unroll")                                                          \
        for (int u_ = 0; u_ < 4; u_++) {                                           \
            int row_ = lrow + u_ * 32;                                             \
            uint32_t so_ = (uint32_t)(((row_ << 3) + (lgrp ^ (row_ & 7))) * 16);   \
            size_t goff_ = (size_t)row_ * Dd + d0_ + lgrp * 8;                     \
            cp16(sbase_ + OFF_AH + so_, g_fh + (size_t)row0 * Dd + goff_);         \
            cp16(sbase_ + OFF_AM + so_, g_fm + (size_t)row0 * Dd + goff_);         \
            cp16(sbase_ + OFF_BH + so_, g_ch + (size_t)nbase * Dd + goff_);        \
            cp16(sbase_ + OFF_BM + so_, g_cm + (size_t)nbase * Dd + goff_);        \
        }                                                                          \
        asm volatile("cp.async.commit_group;" ::: "memory");                       \
    } while (0)

    // ldmatrix address components (16B-granule XOR swizzle within 128B rows)
    int arow_b = wm * 64 + (lane & 7) + ((lane >> 3) & 1) * 8;   // + mt*16
    int agrp_h = (lane >> 4);                                    // + ks*2
    int brow_b = wn * 32 + (lane & 7) + ((lane >> 4) << 3);      // + bt*16
    int bgrp_h = ((lane >> 3) & 1);

    ISSUE_CHUNK(0, 0);

    for (int ch2 = 0; ch2 < NCHK2; ch2++) {
        int stg = ch2 & 1;
        if (ch2 + 1 < NCHK2) {
            ISSUE_CHUNK(ch2 + 1, stg ^ 1);
            asm volatile("cp.async.wait_group 1;" ::: "memory");
        } else {
            asm volatile("cp.async.wait_group 0;" ::: "memory");
        }
        __syncthreads();

        uint32_t sbase = sb + stg * STAGE_BYTES;
#pragma unroll
        for (int ks = 0; ks < KC / 16; ks++) {
            uint32_t ah[4][4], am[4][4], bh[4][2], bm[4][2];
#pragma unroll
            for (int mt = 0; mt < 4; mt++) {
                int row = arow_b + mt * 16;
                int grp = ks * 2 + agrp_h;
                uint32_t so = (uint32_t)(((row << 3) + (grp ^ (row & 7))) * 16);
                ldsm_x4(sbase + OFF_AH + so, ah[mt][0], ah[mt][1], ah[mt][2], ah[mt][3]);
                ldsm_x4(sbase + OFF_AM + so, am[mt][0], am[mt][1], am[mt][2], am[mt][3]);
            }
#pragma unroll
            for (int bt = 0; bt < 2; bt++) {
                int row = brow_b + bt * 16;
                int grp = ks * 2 + bgrp_h;
                uint32_t so = (uint32_t)(((row << 3) + (grp ^ (row & 7))) * 16);
                ldsm_x4(sbase + OFF_BH + so, bh[2 * bt][0], bh[2 * bt][1],
                        bh[2 * bt + 1][0], bh[2 * bt + 1][1]);
                ldsm_x4(sbase + OFF_BM + so, bm[2 * bt][0], bm[2 * bt][1],
                        bm[2 * bt + 1][0], bm[2 * bt + 1][1]);
            }
#pragma unroll
            for (int mt = 0; mt < 4; mt++)
#pragma unroll
                for (int nt = 0; nt < 4; nt++) {
                    mma16816(acc[mt][nt], ah[mt], bh[nt]);   // hh
                    mma16816(acc[mt][nt], ah[mt], bm[nt]);   // hm
                    mma16816(acc[mt][nt], am[mt], bh[nt]);   // mh
                }
        }
        __syncthreads();
    }

    // ---------------- epilogue: distances + argmin ----------------
    int q = lane & 3, hr = lane >> 2;
#pragma unroll
    for (int mt = 0; mt < 4; mt++)
#pragma unroll
        for (int half = 0; half < 2; half++) {
            float bd = 3.4e38f;
            int bi = 0;
#pragma unroll
            for (int nt = 0; nt < 4; nt++)
#pragma unroll
                for (int j = 0; j < 2; j++) {
                    int col = wn * 32 + nt * 8 + 2 * q + j;
                    float dist = scsq[col] - 2.0f * acc[mt][nt][half * 2 + j];
                    if (dist < bd) { bd = dist; bi = col; }
                }
#pragma unroll
            for (int o = 1; o <= 2; o <<= 1) {
                float od = __shfl_xor_sync(0xffffffffu, bd, o);
                int   oi = __shfl_xor_sync(0xffffffffu, bi, o);
                if (od < bd || (od == bd && oi < bi)) { bd = od; bi = oi; }
            }
            if (q == 0) {
                int lr = wm * 64 + mt * 16 + hr + half * 8;
                sdist[lr][wn] = bd;
                sidx[lr][wn] = bi;
            }
        }
    __syncthreads();
    if (tid < TM) {
        float bd = sdist[tid][0];
        int   bi = sidx[tid][0];
#pragma unroll
        for (int s = 1; s < 4; s++) {
            float od = sdist[tid][s];
            int   oi = sidx[tid][s];
            if (od < bd || (od == bd && oi < bi)) { bd = od; bi = oi; }
        }
        g_bd8[blockIdx.y][row0 + tid] = bd;
        g_bi8[blockIdx.y][row0 + tid] = nbase + bi;
    }
}

// combine 8 N-splits; ascending split order + strict < = lowest-index tie-break
__global__ void combine_kernel() {
    int i = blockIdx.x * blockDim.x + threadIdx.x;
    if (i >= Nn) return;
    float bd = g_bd8[0][i];
    int   bi = g_bi8[0][i];
#pragma unroll
    for (int s = 1; s < 8; s++) {
        float d = g_bd8[s][i];
        if (d < bd) { bd = d; bi = g_bi8[s][i]; }
    }
    g_asg[i] = bi;
}

// ---------------- deterministic stable counting sort ----------------
__global__ void histo_kernel() {
    __shared__ int h[Kk];
    int c = blockIdx.x;
    int t = threadIdx.x;
#pragma unroll
    for (int i = t; i < Kk; i += CHUNK) h[i] = 0;
    __syncthreads();
    int k = g_asg[c * CHUNK + t];
    atomicAdd(&h[k], 1);
    __syncthreads();
#pragma unroll
    for (int i = t; i < Kk; i += CHUNK) g_hist[c * Kk + i] = h[i];
}

__global__ void scan_kernel() {
    __shared__ int s[Kk];
    int t = threadIdx.x;
    int total = 0;
    for (int c = 0; c < NCHUNK; c++) total += g_hist[c * Kk + t];
    g_counts[t] = total;
    s[t] = total;
    __syncthreads();
    for (int o = 1; o < Kk; o <<= 1) {
        int v = (t >= o) ? s[t - o] : 0;
        __syncthreads();
        s[t] += v;
        __syncthreads();
    }
    int excl = (t == 0) ? 0 : s[t - 1];
    g_offsets[t] = excl;
    int run = excl;
    for (int c = 0; c < NCHUNK; c++) {
        int h = g_hist[c * Kk + t];
        g_hist[c * Kk + t] = run;
        run += h;
    }
}

__global__ void scatter_kernel() {
    __shared__ int ka[CHUNK];
    int c = blockIdx.x;
    int t = threadIdx.x;
    int i = c * CHUNK + t;
    int k = g_asg[i];
    ka[t] = k;
    __syncthreads();
    int rank = 0;
    for (int j = 0; j < t; j++) rank += (ka[j] == k);
    g_order[g_hist[c * Kk + k] + rank] = i;
}

__global__ void update_kernel(const float* __restrict__ feats) {
    int k = blockIdx.x;
    int cnt = g_counts[k];
    if (cnt == 0) return;
    int start = g_offsets[k];
    float inv = 1.0f / (float)cnt;
    for (int d = threadIdx.x; d < Dd; d += blockDim.x) {
        float s = 0.f;
        for (int j = 0; j < cnt; j++)
            s += feats[(size_t)g_order[start + j] * Dd + d];
        g_cent[(size_t)k * Dd + d] = s * (float)cnt * inv * inv;
    }
}

__global__ void dists_kernel(const float* __restrict__ feats) {
    int k = blockIdx.x;
    int cnt = g_counts[k];
    int start = g_offsets[k];
    for (int d = threadIdx.x; d < Dd; d += blockDim.x) {
        float c = g_cent[(size_t)k * Dd + d];
        float s = 0.f;
        for (int j = 0; j < cnt; j++) {
            float r = feats[(size_t)g_order[start + j] * Dd + d] - c;
            s = fmaf(r, r, s);
        }
        g_dists[(size_t)k * Dd + d] = s;
    }
}

__global__ void reduce1_kernel() {
    double s = 0.0;
    int stride = gridDim.x * blockDim.x;
    for (int i = blockIdx.x * blockDim.x + threadIdx.x; i < Kk * Dd; i += stride)
        s += (double)expf(-g_dists[i] / CONCENTRATION);
    __shared__ double sm[256];
    sm[threadIdx.x] = s;
    __syncthreads();
    for (int o = 128; o; o >>= 1) {
        if (threadIdx.x < o) sm[threadIdx.x] += sm[threadIdx.x + o];
        __syncthreads();
    }
    if (threadIdx.x == 0) g_part1[blockIdx.x] = sm[0];
}

__global__ void finalize1_kernel() {
    __shared__ double sm[256];
    sm[threadIdx.x] = g_part1[threadIdx.x];
    __syncthreads();
    for (int o = 128; o; o >>= 1) {
        if (threadIdx.x < o) sm[threadIdx.x] += sm[threadIdx.x + o];
        __syncthreads();
    }
    if (threadIdx.x == 0) g_S = sm[0];
}

__global__ void reduce2_kernel() {
    float Sf = (float)g_S;
    double e1 = 0.0, e2 = 0.0;
    int stride = gridDim.x * blockDim.x;
    for (int i = blockIdx.x * blockDim.x + threadIdx.x; i < Kk * Dd; i += stride) {
        float dv = g_dists[i];
        float p  = expf(-dv / CONCENTRATION);
        float q  = p / Sf;
        e1 += (double)(q * logf(q + EPSf));
        float p2 = expf(-dv / TEMPERATURE);
        e2 += (double)logf(p2 + EPSf);
    }
    __shared__ double sa[256], sb[256];
    sa[threadIdx.x] = e1;
    sb[threadIdx.x] = e2;
    __syncthreads();
    for (int o = 128; o; o >>= 1) {
        if (threadIdx.x < o) {
            sa[threadIdx.x] += sa[threadIdx.x + o];
            sb[threadIdx.x] += sb[threadIdx.x + o];
        }
        __syncthreads();
    }
    if (threadIdx.x == 0) {
        g_part2a[blockIdx.x] = sa[0];
        g_part2b[blockIdx.x] = sb[0];
    }
}

__global__ void finalize2_kernel(float* __restrict__ out) {
    __shared__ double sa[256], sb[256];
    sa[threadIdx.x] = g_part2a[threadIdx.x];
    sb[threadIdx.x] = g_part2b[threadIdx.x];
    __syncthreads();
    for (int o = 128; o; o >>= 1) {
        if (threadIdx.x < o) {
            sa[threadIdx.x] += sa[threadIdx.x + o];
            sb[threadIdx.x] += sb[threadIdx.x + o];
        }
        __syncthreads();
    }
    if (threadIdx.x == 0) {
        double kd = (double)(Kk * Dd);
        double entropy = (sa[0] / kd);
        double nll = -(sb[0] / kd);
        out[0] = (float)(entropy + nll);
    }
}

extern "C" void kernel_launch(void* const* d_in, const int* in_sizes, int n_in,
                              void* d_out, int out_size) {
    const float* feats = (const float*)d_in[0];
    float* out = (float*)d_out;
    (void)in_sizes; (void)n_in; (void)out_size;

    static bool attr_done = false;
    if (!attr_done) {
        cudaFuncSetAttribute(assign_mma_kernel,
                             cudaFuncAttributeMaxDynamicSharedMemorySize, SMEM_BYTES);
        attr_done = true;
    }

    dim3 agrid(Nn / TM, Kk / TN);

    copy_init_kernel<<<(Kk * Dd + 255) / 256, 256>>>(feats);
    split_feats_kernel<<<(Nn * Dd + 255) / 256, 256>>>(feats);

    for (int it = 0; it < NUM_ITERS; it++) {
        csq_kernel<<<(Kk * 32) / 256, 256>>>();
        split_cent_kernel<<<(Kk * Dd + 255) / 256, 256>>>();
        assign_mma_kernel<<<agrid, 256, SMEM_BYTES>>>();
        combine_kernel<<<Nn / 256, 256>>>();
        histo_kernel<<<NCHUNK, CHUNK>>>();
        scan_kernel<<<1, Kk>>>();
        scatter_kernel<<<NCHUNK, CHUNK>>>();
        update_kernel<<<Kk, 128>>>(feats);
    }

    csq_kernel<<<(Kk * 32) / 256, 256>>>();
    split_cent_kernel<<<(Kk * Dd + 255) / 256, 256>>>();
    assign_mma_kernel<<<agrid, 256, SMEM_BYTES>>>();
    combine_kernel<<<Nn / 256, 256>>>();
    histo_kernel<<<NCHUNK, CHUNK>>>();
    scan_kernel<<<1, Kk>>>();
    scatter_kernel<<<NCHUNK, CHUNK>>>();
    dists_kernel<<<Kk, 128>>>(feats);

    reduce1_kernel<<<256, 256>>>();
    finalize1_kernel<<<1, 256>>>();
    reduce2_kernel<<<256, 256>>>();
    finalize2_kernel<<<1, 256>>>(out);
}